// round 5
// baseline (speedup 1.0000x reference)
#include <cuda_runtime.h>
#include <math.h>

// ---------------- problem constants ----------------
#define NB   2048
#define SQN  64
#define PCN  24
#define FDIM 16
#define HDIM 128
#define DDIM 256
#define TDIM 128
#define ADIM 4672
#define E_ADJ 420
#define E_OCC 24
#define E_ATT 40
#define E_DEF 40
#define E_REV 24
#define N_EDGES (E_ADJ + E_OCC + E_ATT + E_DEF + E_REV)  // 548

// ---------------- scratch (static device globals: allocation-free) ----------------
__device__ float g_shared[NB * DDIM];  // 2 MB
__device__ float g_pt[NB * TDIM];      // 1 MB
__device__ float g_vt[NB * TDIM];      // 1 MB

// jax.nn.gelu default = approximate (tanh) form
__device__ __forceinline__ float gelu_f(float x) {
    float t = tanhf(0.7978845608028654f * (x + 0.044715f * x * x * x));
    return 0.5f * x * (1.0f + t);
}

// ---------------- smem layout for board kernel (floats) ----------------
#define OFF_HSQ  0        // 64*128 = 8192
#define OFF_HPC  8192     // 24*128 = 3072
#define OFF_RADJ 11264    // 64*128
#define OFF_ROCC 19456    // 64*128
#define OFF_RATT 27648    // 24*128
#define OFF_RDEF 30720    // 24*128
#define OFF_RREV 33792    // 24*128
#define OFF_WST  36864    // 128*128 = 16384 (weight staging / x staging)
#define OFF_SACC 53248    // 256
#define OFF_EIDX 53504    // 548 ints
#define SMEM1_BYTES (53504*4 + 548*4)   // 216208 B

// ============================================================================
// Kernel 1: one CTA per board. Fully fused GNN -> g_shared[b][256].
// ============================================================================
__global__ void __launch_bounds__(256, 1) board_kernel(
    const float* __restrict__ x_sq, const float* __restrict__ x_pc,
    const float* __restrict__ W_in_sq, const float* __restrict__ b_in_sq,
    const float* __restrict__ W_in_pc, const float* __restrict__ b_in_pc,
    const float* __restrict__ W_adj, const float* __restrict__ W_occ,
    const float* __restrict__ W_att, const float* __restrict__ W_def,
    const float* __restrict__ W_rev,
    const float* __restrict__ W_out, const float* __restrict__ b_out,
    const int* __restrict__ ei_adj, const int* __restrict__ ei_occ,
    const int* __restrict__ ei_att, const int* __restrict__ ei_def,
    const int* __restrict__ ei_rev)
{
    extern __shared__ float sm[];
    float* h_sq   = sm + OFF_HSQ;
    float* h_pc   = sm + OFF_HPC;
    float* rawAdj = sm + OFF_RADJ;
    float* rawOcc = sm + OFF_ROCC;
    float* rawAtt = sm + OFF_RATT;
    float* rawDef = sm + OFF_RDEF;
    float* rawRev = sm + OFF_RREV;
    float* wst    = sm + OFF_WST;
    float* sacc   = sm + OFF_SACC;
    int*   eidx   = (int*)(sm + OFF_EIDX);

    const int b = blockIdx.x;
    const int t = threadIdx.x;

    // ---- load edges (convert to board-local, pack s | d<<8) ----
    {
        const int ba = b * E_ADJ;
        for (int i = t; i < E_ADJ; i += 256) {
            int s = ei_adj[ba + i] - b * SQN;
            int d = ei_adj[NB * E_ADJ + ba + i] - b * SQN;
            eidx[i] = s | (d << 8);
        }
        const int bo = b * E_OCC;
        for (int i = t; i < E_OCC; i += 256) {
            int s = ei_occ[bo + i] - b * PCN;                  // src: piece
            int d = ei_occ[NB * E_OCC + bo + i] - b * SQN;     // dst: square
            eidx[E_ADJ + i] = s | (d << 8);
        }
        const int bt = b * E_ATT;
        for (int i = t; i < E_ATT; i += 256) {
            int s  = ei_att[bt + i] - b * PCN;
            int d  = ei_att[NB * E_ATT + bt + i] - b * PCN;
            eidx[E_ADJ + E_OCC + i] = s | (d << 8);
            int s2 = ei_def[bt + i] - b * PCN;
            int d2 = ei_def[NB * E_DEF + bt + i] - b * PCN;
            eidx[E_ADJ + E_OCC + E_ATT + i] = s2 | (d2 << 8);
        }
        for (int i = t; i < E_REV; i += 256) {
            int s = ei_rev[bo + i] - b * SQN;                  // src: square
            int d = ei_rev[NB * E_REV + bo + i] - b * PCN;     // dst: piece
            eidx[E_ADJ + E_OCC + E_ATT + E_DEF + i] = s | (d << 8);
        }
    }

    // ---- zero raw buffers (25600 floats) + sacc ----
    {
        float4* r4 = (float4*)rawAdj;
        for (int i = t; i < 6400; i += 256) r4[i] = make_float4(0.f, 0.f, 0.f, 0.f);
        sacc[t & 255] = 0.f;
    }

    // ---- stage x tiles + input weights into wst region ----
    float* xs  = wst;              // 64*16 = 1024
    float* xp  = wst + 1024;       // 24*16 = 384
    float* wi1 = wst + 2048;       // 16*128
    float* wi2 = wst + 4096;       // 16*128
    for (int i = t; i < SQN * FDIM; i += 256) xs[i] = x_sq[b * SQN * FDIM + i];
    for (int i = t; i < PCN * FDIM; i += 256) xp[i] = x_pc[b * PCN * FDIM + i];
    for (int i = t; i < FDIM * HDIM; i += 256) { wi1[i] = W_in_sq[i]; wi2[i] = W_in_pc[i]; }
    __syncthreads();

    // ---- Phase 1: h = gelu(x @ W_in + b_in) ----
    {
        const int c  = t & 127;
        const int rh = t >> 7;  // 0 or 1
        float wcol[16];
        #pragma unroll
        for (int k = 0; k < 16; k++) wcol[k] = wi1[k * 128 + c];
        float bias = b_in_sq[c];
        for (int r = rh * 32; r < rh * 32 + 32; r++) {
            float acc = bias;
            #pragma unroll
            for (int k = 0; k < 16; k++) acc += xs[r * 16 + k] * wcol[k];
            h_sq[r * 128 + c] = gelu_f(acc);
        }
        #pragma unroll
        for (int k = 0; k < 16; k++) wcol[k] = wi2[k * 128 + c];
        bias = b_in_pc[c];
        for (int r = rh * 12; r < rh * 12 + 12; r++) {
            float acc = bias;
            #pragma unroll
            for (int k = 0; k < 16; k++) acc += xp[r * 16 + k] * wcol[k];
            h_pc[r * 128 + c] = gelu_f(acc);
        }
    }
    __syncthreads();

    // ---- Phase 2: raw edge aggregation (column-owner threads, no atomics) ----
    if (t < 128) {
        const int c = t;
        for (int i = 0; i < E_ADJ; i++) {
            int e = eidx[i]; int s = e & 255; int d = e >> 8;
            rawAdj[d * 128 + c] += h_sq[s * 128 + c];
        }
    } else {
        const int c = t - 128;
        const int* ep = eidx + E_ADJ;
        for (int i = 0; i < E_OCC; i++) {
            int e = ep[i]; int s = e & 255; int d = e >> 8;
            rawOcc[d * 128 + c] += h_pc[s * 128 + c];
        }
        ep += E_OCC;
        for (int i = 0; i < E_ATT; i++) {
            int e = ep[i]; int s = e & 255; int d = e >> 8;
            rawAtt[d * 128 + c] += h_pc[s * 128 + c];
        }
        ep += E_ATT;
        for (int i = 0; i < E_DEF; i++) {
            int e = ep[i]; int s = e & 255; int d = e >> 8;
            rawDef[d * 128 + c] += h_pc[s * 128 + c];
        }
        ep += E_DEF;
        for (int i = 0; i < E_REV; i++) {
            int e = ep[i]; int s = e & 255; int d = e >> 8;
            rawRev[d * 128 + c] += h_sq[s * 128 + c];
        }
    }

    const int c4 = (t & 31) * 4;
    const int rg = t >> 5;  // 0..7

    // ---- Phase 3a: agg_sq matmuls + residual + gelu (h_sq -> h2_sq in place) ----
    {
        float C[8][4];
        #pragma unroll
        for (int i = 0; i < 8; i++)
            #pragma unroll
            for (int j = 0; j < 4; j++) C[i][j] = 0.f;

        #pragma unroll
        for (int w = 0; w < 2; w++) {
            __syncthreads();  // wst free / raw complete (w==0), wst consumed (w==1)
            const float4* srcw = (const float4*)(w == 0 ? W_adj : W_occ);
            float4* w4 = (float4*)wst;
            for (int i = t; i < 4096; i += 256) w4[i] = srcw[i];
            __syncthreads();
            const float* raw = (w == 0) ? rawAdj : rawOcc;
            #pragma unroll 4
            for (int k = 0; k < 128; k++) {
                float4 bv = *(const float4*)&wst[k * 128 + c4];
                #pragma unroll
                for (int i = 0; i < 8; i++) {
                    float a = raw[(rg * 8 + i) * 128 + k];
                    C[i][0] += a * bv.x; C[i][1] += a * bv.y;
                    C[i][2] += a * bv.z; C[i][3] += a * bv.w;
                }
            }
        }
        #pragma unroll
        for (int i = 0; i < 8; i++) {
            int r = rg * 8 + i;
            #pragma unroll
            for (int j = 0; j < 4; j++) {
                float v = h_sq[r * 128 + c4 + j] + C[i][j];
                h_sq[r * 128 + c4 + j] = gelu_f(v);
            }
        }
    }

    // ---- Phase 3b: agg_pc matmuls + residual + gelu (h_pc -> h2_pc) ----
    {
        float C[3][4];
        #pragma unroll
        for (int i = 0; i < 3; i++)
            #pragma unroll
            for (int j = 0; j < 4; j++) C[i][j] = 0.f;

        #pragma unroll
        for (int w = 0; w < 3; w++) {
            __syncthreads();
            const float4* srcw = (const float4*)(w == 0 ? W_att : (w == 1 ? W_def : W_rev));
            float4* w4 = (float4*)wst;
            for (int i = t; i < 4096; i += 256) w4[i] = srcw[i];
            __syncthreads();
            const float* raw = (w == 0) ? rawAtt : (w == 1 ? rawDef : rawRev);
            #pragma unroll 4
            for (int k = 0; k < 128; k++) {
                float4 bv = *(const float4*)&wst[k * 128 + c4];
                #pragma unroll
                for (int i = 0; i < 3; i++) {
                    float a = raw[(rg * 3 + i) * 128 + k];
                    C[i][0] += a * bv.x; C[i][1] += a * bv.y;
                    C[i][2] += a * bv.z; C[i][3] += a * bv.w;
                }
            }
        }
        #pragma unroll
        for (int i = 0; i < 3; i++) {
            int r = rg * 3 + i;
            #pragma unroll
            for (int j = 0; j < 4; j++) {
                float v = h_pc[r * 128 + c4 + j] + C[i][j];
                h_pc[r * 128 + c4 + j] = gelu_f(v);
            }
        }
    }

    // ---- Phase 4: out = gelu(h2 @ W_out + b_out); board-mean into sacc ----
    #pragma unroll
    for (int h = 0; h < 2; h++) {
        __syncthreads();  // h2 complete (h==0) / wst consumed (h==1)
        {
            float4* w4 = (float4*)wst;
            const float4* src = (const float4*)W_out;  // (128,256): 64 float4 per row
            for (int m = t; m < 4096; m += 256) {
                int k = m >> 5, j4 = m & 31;
                w4[m] = src[k * 64 + h * 32 + j4];
            }
        }
        __syncthreads();
        // squares: 64 x 128(half), thread tile 8x4
        {
            float C[8][4];
            #pragma unroll
            for (int i = 0; i < 8; i++)
                #pragma unroll
                for (int j = 0; j < 4; j++) C[i][j] = 0.f;
            #pragma unroll 4
            for (int k = 0; k < 128; k++) {
                float4 bv = *(const float4*)&wst[k * 128 + c4];
                #pragma unroll
                for (int i = 0; i < 8; i++) {
                    float a = h_sq[(rg * 8 + i) * 128 + k];
                    C[i][0] += a * bv.x; C[i][1] += a * bv.y;
                    C[i][2] += a * bv.z; C[i][3] += a * bv.w;
                }
            }
            #pragma unroll
            for (int j = 0; j < 4; j++) {
                int cg = h * 128 + c4 + j;
                float bo = b_out[cg];
                float s = 0.f;
                #pragma unroll
                for (int i = 0; i < 8; i++) s += gelu_f(C[i][j] + bo);
                atomicAdd(&sacc[cg], s * (1.0f / 64.0f));
            }
        }
        // pieces: 24 x 128(half), thread tile 3x4
        {
            float C[3][4];
            #pragma unroll
            for (int i = 0; i < 3; i++)
                #pragma unroll
                for (int j = 0; j < 4; j++) C[i][j] = 0.f;
            #pragma unroll 4
            for (int k = 0; k < 128; k++) {
                float4 bv = *(const float4*)&wst[k * 128 + c4];
                #pragma unroll
                for (int i = 0; i < 3; i++) {
                    float a = h_pc[(rg * 3 + i) * 128 + k];
                    C[i][0] += a * bv.x; C[i][1] += a * bv.y;
                    C[i][2] += a * bv.z; C[i][3] += a * bv.w;
                }
            }
            #pragma unroll
            for (int j = 0; j < 4; j++) {
                int cg = h * 128 + c4 + j;
                float bo = b_out[cg];
                float s = 0.f;
                #pragma unroll
                for (int i = 0; i < 3; i++) s += gelu_f(C[i][j] + bo);
                atomicAdd(&sacc[cg], s * (1.0f / 24.0f));
            }
        }
    }
    __syncthreads();
    g_shared[b * DDIM + t] = sacc[t];  // t covers 0..255 == DDIM
}

// ============================================================================
// Kernel 2: pt = gelu(shared @ W_pt + b_pt), vt = gelu(shared @ W_vt + b_vt)
// 16 rows per block, grid 128.
// ============================================================================
#define SMEM2_BYTES ((4096 + 32768) * 4)
__global__ void __launch_bounds__(256) heads_kernel(
    const float* __restrict__ W_pt, const float* __restrict__ b_pt,
    const float* __restrict__ W_vt, const float* __restrict__ b_vt)
{
    extern __shared__ float sm[];
    float* At = sm;          // 16*256
    float* Bt = sm + 4096;   // 256*128
    const int t = threadIdx.x;
    const int r0 = blockIdx.x * 16;

    for (int i = t; i < 16 * 256; i += 256) At[i] = g_shared[r0 * 256 + i];

    const int c4 = (t & 31) * 4;
    const int rg = t >> 5;  // 0..7 -> rows rg*2, rg*2+1

    #pragma unroll
    for (int w = 0; w < 2; w++) {
        __syncthreads();
        const float* W  = w ? W_vt : W_pt;
        const float* bb = w ? b_vt : b_pt;
        float* outp     = w ? g_vt : g_pt;
        for (int i = t; i < 256 * 128; i += 256) Bt[i] = W[i];
        __syncthreads();
        float C[2][4] = {{0.f, 0.f, 0.f, 0.f}, {0.f, 0.f, 0.f, 0.f}};
        #pragma unroll 4
        for (int k = 0; k < 256; k++) {
            float4 bv = *(const float4*)&Bt[k * 128 + c4];
            float a0 = At[(rg * 2) * 256 + k];
            float a1 = At[(rg * 2 + 1) * 256 + k];
            C[0][0] += a0 * bv.x; C[0][1] += a0 * bv.y; C[0][2] += a0 * bv.z; C[0][3] += a0 * bv.w;
            C[1][0] += a1 * bv.x; C[1][1] += a1 * bv.y; C[1][2] += a1 * bv.z; C[1][3] += a1 * bv.w;
        }
        #pragma unroll
        for (int i = 0; i < 2; i++) {
            int r = r0 + rg * 2 + i;
            float4 o;
            o.x = gelu_f(C[i][0] + bb[c4 + 0]);
            o.y = gelu_f(C[i][1] + bb[c4 + 1]);
            o.z = gelu_f(C[i][2] + bb[c4 + 2]);
            o.w = gelu_f(C[i][3] + bb[c4 + 3]);
            *(float4*)&outp[r * 128 + c4] = o;
        }
    }
}

// ============================================================================
// Kernel 3: policy = pt @ W_ph + b_ph  (2048 x 4672, K=128)
// block = 64 rows x 128 cols, grid (37, 32)
// ============================================================================
#define SMEM3_BYTES ((8192 + 16384) * 4)
__global__ void __launch_bounds__(256) policy_kernel(
    const float* __restrict__ W_ph, const float* __restrict__ b_ph,
    float* __restrict__ out)
{
    extern __shared__ float sm[];
    float* At = sm;          // 64*128
    float* Bt = sm + 8192;   // 128*128
    const int t = threadIdx.x;
    const int rb = blockIdx.y * 64;
    const int cb = blockIdx.x * 128;

    for (int i = t; i < 64 * 128; i += 256) At[i] = g_pt[rb * 128 + i];
    for (int m = t; m < 128 * 128; m += 256) {
        int k = m >> 7, j = m & 127;
        int col = cb + j;
        Bt[m] = (col < ADIM) ? W_ph[k * ADIM + col] : 0.f;
    }
    __syncthreads();

    const int c4 = (t & 31) * 4;
    const int rg = t >> 5;
    float C[8][4];
    #pragma unroll
    for (int i = 0; i < 8; i++)
        #pragma unroll
        for (int j = 0; j < 4; j++) C[i][j] = 0.f;

    #pragma unroll 4
    for (int k = 0; k < 128; k++) {
        float4 bv = *(const float4*)&Bt[k * 128 + c4];
        #pragma unroll
        for (int i = 0; i < 8; i++) {
            float a = At[(rg * 8 + i) * 128 + k];
            C[i][0] += a * bv.x; C[i][1] += a * bv.y;
            C[i][2] += a * bv.z; C[i][3] += a * bv.w;
        }
    }
    #pragma unroll
    for (int i = 0; i < 8; i++) {
        int r = rb + rg * 8 + i;
        #pragma unroll
        for (int j = 0; j < 4; j++) {
            int col = cb + c4 + j;
            if (col < ADIM) out[r * ADIM + col] = C[i][j] + b_ph[col];
        }
    }
}

// ============================================================================
// Kernel 4: value = tanh(vt @ W_vh + b_vh)  (2048 x 1)
// ============================================================================
__global__ void __launch_bounds__(256) value_kernel(
    const float* __restrict__ W_vh, const float* __restrict__ b_vh,
    float* __restrict__ out)
{
    int r = blockIdx.x * 8 + (threadIdx.x >> 5);
    int lane = threadIdx.x & 31;
    float acc = 0.f;
    #pragma unroll
    for (int q = 0; q < 4; q++)
        acc += g_vt[r * 128 + q * 32 + lane] * W_vh[q * 32 + lane];
    #pragma unroll
    for (int o = 16; o; o >>= 1) acc += __shfl_xor_sync(0xffffffffu, acc, o);
    if (lane == 0) out[(size_t)NB * ADIM + r] = tanhf(acc + b_vh[0]);
}

// ============================================================================
extern "C" void kernel_launch(void* const* d_in, const int* in_sizes, int n_in,
                              void* d_out, int out_size) {
    (void)in_sizes; (void)n_in; (void)out_size;
    const float* x_sq    = (const float*)d_in[0];
    const float* x_pc    = (const float*)d_in[1];
    const float* W_in_sq = (const float*)d_in[2];
    const float* b_in_sq = (const float*)d_in[3];
    const float* W_in_pc = (const float*)d_in[4];
    const float* b_in_pc = (const float*)d_in[5];
    const float* W_adj   = (const float*)d_in[6];
    const float* W_occ   = (const float*)d_in[7];
    const float* W_att   = (const float*)d_in[8];
    const float* W_def   = (const float*)d_in[9];
    const float* W_rev   = (const float*)d_in[10];
    const float* W_out   = (const float*)d_in[11];
    const float* b_out   = (const float*)d_in[12];
    const float* W_pt    = (const float*)d_in[13];
    const float* b_pt    = (const float*)d_in[14];
    const float* W_vt    = (const float*)d_in[15];
    const float* b_vt    = (const float*)d_in[16];
    const float* W_ph    = (const float*)d_in[17];
    const float* b_ph    = (const float*)d_in[18];
    const float* W_vh    = (const float*)d_in[19];
    const float* b_vh    = (const float*)d_in[20];
    const int* ei_adj    = (const int*)d_in[21];
    const int* ei_occ    = (const int*)d_in[22];
    const int* ei_att    = (const int*)d_in[23];
    const int* ei_def    = (const int*)d_in[24];
    const int* ei_rev    = (const int*)d_in[25];
    float* out = (float*)d_out;

    cudaFuncSetAttribute(board_kernel,  cudaFuncAttributeMaxDynamicSharedMemorySize, SMEM1_BYTES);
    cudaFuncSetAttribute(heads_kernel,  cudaFuncAttributeMaxDynamicSharedMemorySize, SMEM2_BYTES);
    cudaFuncSetAttribute(policy_kernel, cudaFuncAttributeMaxDynamicSharedMemorySize, SMEM3_BYTES);

    board_kernel<<<NB, 256, SMEM1_BYTES>>>(
        x_sq, x_pc, W_in_sq, b_in_sq, W_in_pc, b_in_pc,
        W_adj, W_occ, W_att, W_def, W_rev, W_out, b_out,
        ei_adj, ei_occ, ei_att, ei_def, ei_rev);

    heads_kernel<<<NB / 16, 256, SMEM2_BYTES>>>(W_pt, b_pt, W_vt, b_vt);

    policy_kernel<<<dim3((ADIM + 127) / 128, NB / 64), 256, SMEM3_BYTES>>>(W_ph, b_ph, out);

    value_kernel<<<NB / 8, 256>>>(W_vh, b_vh, out);
}